// round 11
// baseline (speedup 1.0000x reference)
#include <cuda_runtime.h>

#define THREADS   512
#define MROWS     8           // batch rows per CTA
#define DIMV      128         // DATA + AUG
#define WIDTHV    256
#define DATAV     64
#define BATCH     2048
#define TSTEPS    128
#define SUBSTEPS  4
#define MD        (MROWS*DIMV)    // 1024
#define GRIDN     (BATCH/MROWS)   // 256

typedef unsigned long long ull;

// packed fp32x2 FMA: d = a*b + d
#define FMA2(d, a, b) asm("fma.rn.f32x2 %0, %1, %2, %0;" : "+l"(d) : "l"(a), "l"(b))
#define PACK2(d, s)   asm("mov.b64 %0, {%1, %1};" : "=l"(d) : "r"(s))

// k-major (transposed) weight copies
static __device__ float g_W1t[DIMV * WIDTHV + 16];    // [k<128][j<256]
static __device__ float g_W2t[WIDTHV * WIDTHV + 16];  // [k<256][j<256]
static __device__ float g_W3t[WIDTHV * DIMV + 16];    // [k<256][j<128]

__global__ void transpose_weights(const float* __restrict__ W1,
                                  const float* __restrict__ W2,
                                  const float* __restrict__ W3)
{
    int stride = gridDim.x * blockDim.x;
    int i0 = blockIdx.x * blockDim.x + threadIdx.x;
    for (int t = i0; t < WIDTHV * DIMV; t += stride) {       // W1[j<256][k<128]
        int j = t >> 7, k = t & 127;
        g_W1t[k * WIDTHV + j] = W1[t];
    }
    for (int t = i0; t < WIDTHV * WIDTHV; t += stride) {     // W2[j<256][k<256]
        int j = t >> 8, k = t & 255;
        g_W2t[k * WIDTHV + j] = W2[t];
    }
    for (int t = i0; t < DIMV * WIDTHV; t += stride) {       // W3[j<128][k<256]
        int j = t >> 8, k = t & 255;
        g_W3t[k * DIMV + j] = W3[t];
    }
}

// ---------------------------------------------------------------------------
// One layer: out[j][m] = act( sum_k in[k][m] * Wt[k][j] + b[j] )
// Activations channel-major [k][8 rows]: every activation LDS is a warp
// broadcast (k warp-uniform); row-pairs are f32x2-adjacent.
// TN=2 columns/thread, TM=8 rows (4 f32x2 pairs). K split across G groups
// (g = tid/CT, warp-uniform). Partials in a stride-17 smem buffer, written
// as SCALAR floats (stride 17 odd -> lane*17 mod 32 is a permutation ->
// conflict-free STS.32; float2 STS here would be 8B-misaligned for odd tid).
// ---------------------------------------------------------------------------
template<int N, int K, int G, bool RELU>
__device__ __forceinline__ void layer(const float* __restrict__ act,
                                      float* __restrict__ outp,
                                      const float* __restrict__ Wt,
                                      const float* __restrict__ bias,
                                      float* __restrict__ red, int tid)
{
    constexpr int CT = N / 2;      // column-threads (each owns 2 cols)
    constexpr int KR = K / G;      // k-range per group
    static_assert(CT * G == THREADS, "thread mapping");
    const int g  = tid / CT;       // warp-uniform
    const int ct = tid % CT;
    const int k0 = g * KR;

    ull a00 = 0, a10 = 0, a20 = 0, a30 = 0;   // col 0, row pairs 0..3
    ull a01 = 0, a11 = 0, a21 = 0, a31 = 0;   // col 1

    const float2* wp = reinterpret_cast<const float2*>(Wt) + ct;  // lane-contiguous

#pragma unroll 4
    for (int k = k0; k < k0 + KR; ++k) {
        float2 w = __ldg(wp + k * CT);
        ull wd0, wd1;
        PACK2(wd0, __float_as_uint(w.x));
        PACK2(wd1, __float_as_uint(w.y));

        const ulonglong2* ap = reinterpret_cast<const ulonglong2*>(act + k * MROWS);
        ulonglong2 v0 = ap[0], v1 = ap[1];     // 8 rows, broadcast LDS

        FMA2(a00, v0.x, wd0);  FMA2(a01, v0.x, wd1);
        FMA2(a10, v0.y, wd0);  FMA2(a11, v0.y, wd1);
        FMA2(a20, v1.x, wd0);  FMA2(a21, v1.x, wd1);
        FMA2(a30, v1.y, wd0);  FMA2(a31, v1.y, wd1);
    }

    // partials: 16 floats per writer, stride-17 rows, SCALAR stores (aligned,
    // conflict-free: 17 odd)
    {
        float* rr = red + tid * 17;
        float2 t0 = *reinterpret_cast<float2*>(&a00);
        float2 t1 = *reinterpret_cast<float2*>(&a10);
        float2 t2 = *reinterpret_cast<float2*>(&a20);
        float2 t3 = *reinterpret_cast<float2*>(&a30);
        float2 t4 = *reinterpret_cast<float2*>(&a01);
        float2 t5 = *reinterpret_cast<float2*>(&a11);
        float2 t6 = *reinterpret_cast<float2*>(&a21);
        float2 t7 = *reinterpret_cast<float2*>(&a31);
        rr[0]  = t0.x; rr[1]  = t0.y;
        rr[2]  = t1.x; rr[3]  = t1.y;
        rr[4]  = t2.x; rr[5]  = t2.y;
        rr[6]  = t3.x; rr[7]  = t3.y;
        rr[8]  = t4.x; rr[9]  = t4.y;
        rr[10] = t5.x; rr[11] = t5.y;
        rr[12] = t6.x; rr[13] = t6.y;
        rr[14] = t7.x; rr[15] = t7.y;
    }
    __syncthreads();

    // reduce G partials, add bias, activation; outputs linear in [j][m]
    constexpr int NO = N * MROWS;
#pragma unroll
    for (int r = 0; r < NO / THREADS; ++r) {
        int o  = tid + r * THREADS;
        int jj = o >> 3, mm = o & 7;
        int woff = (jj >> 1) * 17 + (jj & 1) * 8 + mm;
        float s = bias[jj];
#pragma unroll
        for (int gg = 0; gg < G; ++gg)
            s += red[gg * CT * 17 + woff];
        if (RELU) s = fmaxf(s, 0.0f);
        outp[o] = s;
    }
    __syncthreads();
}

__device__ __forceinline__ void eval_f(const float* __restrict__ in,
                                       float* __restrict__ outk,
                                       float* __restrict__ h1, float* __restrict__ h2,
                                       float* __restrict__ red,
                                       const float* b1s, const float* b2s,
                                       const float* b3s, int tid)
{
    layer<WIDTHV, DIMV,   4, true >(in, h1, g_W1t, b1s, red, tid);
    layer<WIDTHV, WIDTHV, 4, true >(h1, h2, g_W2t, b2s, red, tid);
    layer<DIMV,   WIDTHV, 8, false>(h2, outk, g_W3t, b3s, red, tid);
}

// dst = y + dt * sum_s c[s] * ks[s]  ([k][m] layout throughout)
template<int NS>
__device__ __forceinline__ void combine(float* __restrict__ dst,
                                        const float* __restrict__ y,
                                        const float* __restrict__ ks,
                                        float dt, const float* c, int tid)
{
#pragma unroll
    for (int r = 0; r < MD / THREADS; ++r) {
        int i = tid + r * THREADS;
        float v = y[i];
#pragma unroll
        for (int s = 0; s < NS; ++s)
            v = fmaf(dt * c[s], ks[s * MD + i], v);
        dst[i] = v;
    }
}

// write data channels (first 64) of all 8 rows for save time t
// tid = m*64 + c -> consecutive lanes write consecutive channels (coalesced)
__device__ __forceinline__ void save_state(const float* __restrict__ y,
                                           float* __restrict__ out,
                                           int base, int t, int tid)
{
    int m = tid >> 6;
    int c = tid & 63;
    out[((size_t)t * BATCH + base + m) * DATAV + c] = y[c * MROWS + m];
}

extern "C" __global__ void __launch_bounds__(THREADS, 2)
anode_kernel(const float* __restrict__ ts, const float* __restrict__ y0,
             const float* __restrict__ b1, const float* __restrict__ b2,
             const float* __restrict__ b3,
             float* __restrict__ out, int out_size)
{
    extern __shared__ float sm[];
    float* tssm = sm;                        // 128
    float* b1s  = tssm + 128;                // 256
    float* b2s  = b1s + 256;                 // 256
    float* b3s  = b2s + 256;                 // 128
    float* y    = b3s + 128;                 // MD (1024)
    float* ytmp = y    + MD;                 // 1024
    float* h1   = ytmp + MD;                 // 2048
    float* h2   = h1   + MROWS * WIDTHV;     // 2048
    float* ks   = h2   + MROWS * WIDTHV;     // 6*MD = 6144
    float* red  = ks   + 6 * MD;             // 512*17 = 8704

    const int tid  = threadIdx.x;
    const int base = blockIdx.x * MROWS;

    if (tid < TSTEPS) tssm[tid] = ts[tid];
    if (tid < WIDTHV) { b1s[tid] = b1[tid]; b2s[tid] = b2[tid]; }
    if (tid < DIMV)   b3s[tid] = b3[tid];

    // load batch tile, transposing to [channel][m]
    {
        int m  = tid & 7;
        int c2 = (tid >> 3) << 1;   // 64 groups * 2 = DIMV channels
        float2 v = *reinterpret_cast<const float2*>(y0 + (size_t)(base + m) * DIMV + c2);
        y[(c2 + 0) * MROWS + m] = v.x;
        y[(c2 + 1) * MROWS + m] = v.y;
    }
    __syncthreads();

    save_state(y, out, base, 0, tid);

    // Dopri5 tableau
    const float c2_[1] = {0.2f};
    const float c3_[2] = {3.f/40.f, 9.f/40.f};
    const float c4_[3] = {44.f/45.f, -56.f/15.f, 32.f/9.f};
    const float c5_[4] = {19372.f/6561.f, -25360.f/2187.f, 64448.f/6561.f, -212.f/729.f};
    const float c6_[5] = {9017.f/3168.f, -355.f/33.f, 46732.f/5247.f, 49.f/176.f, -5103.f/18656.f};
    const float cb_[6] = {35.f/384.f, 0.f, 500.f/1113.f, 125.f/192.f, -2187.f/6784.f, 11.f/84.f};

#pragma unroll 1
    for (int t = 1; t < TSTEPS; ++t) {
        float dt = (tssm[t] - tssm[t - 1]) * (1.0f / SUBSTEPS);
#pragma unroll 1
        for (int s = 0; s < SUBSTEPS; ++s) {
            eval_f(y,    ks + 0 * MD, h1, h2, red, b1s, b2s, b3s, tid);
            combine<1>(ytmp, y, ks, dt, c2_, tid);  __syncthreads();
            eval_f(ytmp, ks + 1 * MD, h1, h2, red, b1s, b2s, b3s, tid);
            combine<2>(ytmp, y, ks, dt, c3_, tid);  __syncthreads();
            eval_f(ytmp, ks + 2 * MD, h1, h2, red, b1s, b2s, b3s, tid);
            combine<3>(ytmp, y, ks, dt, c4_, tid);  __syncthreads();
            eval_f(ytmp, ks + 3 * MD, h1, h2, red, b1s, b2s, b3s, tid);
            combine<4>(ytmp, y, ks, dt, c5_, tid);  __syncthreads();
            eval_f(ytmp, ks + 4 * MD, h1, h2, red, b1s, b2s, b3s, tid);
            combine<5>(ytmp, y, ks, dt, c6_, tid);  __syncthreads();
            eval_f(ytmp, ks + 5 * MD, h1, h2, red, b1s, b2s, b3s, tid);
            combine<6>(y, y, ks, dt, cb_, tid);     __syncthreads();
        }
        save_state(y, out, base, t, tid);
    }

    // second reference output: num_steps = (T-1)*SUBSTEPS = 508
    if (blockIdx.x == 0 && tid == 0) {
        const long long TOT = (long long)TSTEPS * BATCH * DATAV;
        for (long long i = TOT; i < (long long)out_size; ++i)
            out[i] = 508.0f;
    }
}

extern "C" void kernel_launch(void* const* d_in, const int* in_sizes, int n_in,
                              void* d_out, int out_size)
{
    const float* ts = (const float*)d_in[0];
    const float* y0 = (const float*)d_in[1];
    const float* W1 = (const float*)d_in[2];
    const float* b1 = (const float*)d_in[3];
    const float* W2 = (const float*)d_in[4];
    const float* b2 = (const float*)d_in[5];
    const float* W3 = (const float*)d_in[6];
    const float* b3 = (const float*)d_in[7];
    float* out = (float*)d_out;

    transpose_weights<<<256, 256>>>(W1, W2, W3);

    // smem floats: 768 + 2*1024 + 2*2048 + 6144 + 8704 = 21760 -> 87,040 B/CTA
    const int smem_bytes = (768 + 2 * MD + 2 * MROWS * WIDTHV + 6 * MD + THREADS * 17)
                           * (int)sizeof(float);
    cudaFuncSetAttribute(anode_kernel,
                         cudaFuncAttributeMaxDynamicSharedMemorySize, smem_bytes);

    anode_kernel<<<GRIDN, THREADS, smem_bytes>>>(ts, y0, b1, b2, b3, out, out_size);
}

// round 13
// speedup vs baseline: 1.2693x; 1.2693x over previous
#include <cuda_runtime.h>

#define THREADS   512
#define MROWS     16          // batch rows per CTA (TM=16 is load-bearing)
#define DIMV      128         // DATA + AUG
#define WIDTHV    256
#define DATAV     64
#define BATCH     2048
#define TSTEPS    128
#define SUBSTEPS  4
#define MD        (MROWS*DIMV)    // 2048
#define GRIDN     (BATCH/MROWS)   // 128

typedef unsigned long long ull;

// packed fp32x2 FMA: d = a*b + d
#define FMA2(d, a, b) asm("fma.rn.f32x2 %0, %1, %2, %0;" : "+l"(d) : "l"(a), "l"(b))
#define PACK2(d, s)   asm("mov.b64 %0, {%1, %1};" : "=l"(d) : "r"(s))

// k-major (transposed) weight copies
static __device__ float g_W1t[DIMV * WIDTHV + 16];    // [k<128][j<256]
static __device__ float g_W2t[WIDTHV * WIDTHV + 16];  // [k<256][j<256]
static __device__ float g_W3t[WIDTHV * DIMV + 16];    // [k<256][j<128]

__global__ void transpose_weights(const float* __restrict__ W1,
                                  const float* __restrict__ W2,
                                  const float* __restrict__ W3)
{
    int stride = gridDim.x * blockDim.x;
    int i0 = blockIdx.x * blockDim.x + threadIdx.x;
    for (int t = i0; t < WIDTHV * DIMV; t += stride) {       // W1[j<256][k<128]
        int j = t >> 7, k = t & 127;
        g_W1t[k * WIDTHV + j] = W1[t];
    }
    for (int t = i0; t < WIDTHV * WIDTHV; t += stride) {     // W2[j<256][k<256]
        int j = t >> 8, k = t & 255;
        g_W2t[k * WIDTHV + j] = W2[t];
    }
    for (int t = i0; t < DIMV * WIDTHV; t += stride) {       // W3[j<128][k<256]
        int j = t >> 8, k = t & 255;
        g_W3t[k * DIMV + j] = W3[t];
    }
}

// ---------------------------------------------------------------------------
// Hidden layer (N=256): out[j][m] = relu( sum_k in[k][m]*Wt[k][j] + b[j] )
// Channel-major acts [k][16 rows]: LDS are warp broadcasts, rows f32x2-paired.
// TN=2 cols/thread, TM=16 rows (8 f32x2). K split G=4 (g warp-uniform).
// Partials: 32 scalar floats per writer, stride-33 rows (conflict-free).
// ---------------------------------------------------------------------------
template<int K>
__device__ __forceinline__ void layer256(const float* __restrict__ act,
                                         float* __restrict__ outp,
                                         const float* __restrict__ Wt,
                                         const float* __restrict__ bias,
                                         float* __restrict__ red, int tid)
{
    constexpr int CT = 128;        // N/2
    constexpr int G  = 4;
    constexpr int KR = K / G;
    const int g  = tid >> 7;       // warp-uniform
    const int ct = tid & 127;
    const int k0 = g * KR;

    ull acc[8][2];
#pragma unroll
    for (int p = 0; p < 8; ++p) { acc[p][0] = 0ull; acc[p][1] = 0ull; }

    const float2* wp = reinterpret_cast<const float2*>(Wt) + ct;

#pragma unroll 8
    for (int k = k0; k < k0 + KR; ++k) {
        float2 w = __ldg(wp + k * CT);
        ull wd0, wd1;
        PACK2(wd0, __float_as_uint(w.x));
        PACK2(wd1, __float_as_uint(w.y));

        const ulonglong2* ap = reinterpret_cast<const ulonglong2*>(act + k * MROWS);
        ulonglong2 a0 = ap[0], a1 = ap[1], a2 = ap[2], a3 = ap[3];
        ull av[8] = { a0.x, a0.y, a1.x, a1.y, a2.x, a2.y, a3.x, a3.y };

#pragma unroll
        for (int p = 0; p < 8; ++p) {
            FMA2(acc[p][0], av[p], wd0);
            FMA2(acc[p][1], av[p], wd1);
        }
    }

    {   // scalar stores, stride-33 rows
        float* rr = red + tid * 33;
#pragma unroll
        for (int c = 0; c < 2; ++c)
#pragma unroll
            for (int p = 0; p < 8; ++p) {
                float2 v = *reinterpret_cast<float2*>(&acc[p][c]);
                rr[c * 16 + 2 * p]     = v.x;
                rr[c * 16 + 2 * p + 1] = v.y;
            }
    }
    __syncthreads();

    // reduce 4 partials + bias + relu; outputs linear in [j][m]
#pragma unroll
    for (int r = 0; r < (256 * MROWS) / THREADS; ++r) {
        int o  = tid + r * THREADS;
        int jj = o >> 4, mm = o & 15;
        int woff = (jj >> 1) * 33 + (jj & 1) * 16 + mm;
        float s = bias[jj]
                + red[0 * CT * 33 + woff] + red[1 * CT * 33 + woff]
                + red[2 * CT * 33 + woff] + red[3 * CT * 33 + woff];
        outp[o] = fmaxf(s, 0.0f);
    }
    __syncthreads();
}

// ---------------------------------------------------------------------------
// Output layer (N=128, K=256, G=8) with FUSED Runge-Kutta combine epilogue:
// the reduce writes k_{NS-1}[o] AND dst[o] = y[o] + dt*sum_{s<NS} c[s]*k_s[o].
// Saves a separate combine pass + barrier per stage.
// ---------------------------------------------------------------------------
template<int NS>
__device__ __forceinline__ void layer_out_fused(const float* __restrict__ h2,
                                                float* __restrict__ ks,
                                                const float* __restrict__ y,
                                                float* __restrict__ dst,
                                                const float* __restrict__ bias,
                                                float* __restrict__ red,
                                                float dt, const float* cf, int tid)
{
    constexpr int CT = 64;         // N/2
    constexpr int G  = 8;
    constexpr int KR = WIDTHV / G; // 32
    const int g  = tid >> 6;       // warp-uniform
    const int ct = tid & 63;
    const int k0 = g * KR;

    ull acc[8][2];
#pragma unroll
    for (int p = 0; p < 8; ++p) { acc[p][0] = 0ull; acc[p][1] = 0ull; }

    const float2* wp = reinterpret_cast<const float2*>(g_W3t) + ct;

#pragma unroll 8
    for (int k = k0; k < k0 + KR; ++k) {
        float2 w = __ldg(wp + k * CT);
        ull wd0, wd1;
        PACK2(wd0, __float_as_uint(w.x));
        PACK2(wd1, __float_as_uint(w.y));

        const ulonglong2* ap = reinterpret_cast<const ulonglong2*>(h2 + k * MROWS);
        ulonglong2 a0 = ap[0], a1 = ap[1], a2 = ap[2], a3 = ap[3];
        ull av[8] = { a0.x, a0.y, a1.x, a1.y, a2.x, a2.y, a3.x, a3.y };

#pragma unroll
        for (int p = 0; p < 8; ++p) {
            FMA2(acc[p][0], av[p], wd0);
            FMA2(acc[p][1], av[p], wd1);
        }
    }

    {
        float* rr = red + tid * 33;
#pragma unroll
        for (int c = 0; c < 2; ++c)
#pragma unroll
            for (int p = 0; p < 8; ++p) {
                float2 v = *reinterpret_cast<float2*>(&acc[p][c]);
                rr[c * 16 + 2 * p]     = v.x;
                rr[c * 16 + 2 * p + 1] = v.y;
            }
    }
    __syncthreads();

    float dtc[NS];
#pragma unroll
    for (int ss = 0; ss < NS; ++ss) dtc[ss] = dt * cf[ss];

    // reduce 8 partials + bias -> k value; fuse RK combine; [j][m] linear
#pragma unroll
    for (int r = 0; r < (DIMV * MROWS) / THREADS; ++r) {  // 4 iters
        int o  = tid + r * THREADS;
        int jj = o >> 4, mm = o & 15;
        int woff = (jj >> 1) * 33 + (jj & 1) * 16 + mm;
        float s = bias[jj];
#pragma unroll
        for (int gg = 0; gg < G; ++gg)
            s += red[gg * CT * 33 + woff];
        ks[(NS - 1) * MD + o] = s;

        float v = fmaf(dtc[NS - 1], s, y[o]);
#pragma unroll
        for (int ss = 0; ss < NS - 1; ++ss) {
            if (NS == 6 && ss == 1) continue;   // cb[1] == 0
            v = fmaf(dtc[ss], ks[ss * MD + o], v);
        }
        dst[o] = v;
    }
    __syncthreads();
}

// write data channels (first 64) of all 16 rows for save time t (coalesced)
__device__ __forceinline__ void save_state(const float* __restrict__ y,
                                           float* __restrict__ out,
                                           int base, int t, int tid)
{
#pragma unroll
    for (int r = 0; r < (MROWS * DATAV) / THREADS; ++r) {   // 2 iters
        int i = tid + r * THREADS;
        int m = i >> 6, c = i & 63;
        out[((size_t)t * BATCH + base + m) * DATAV + c] = y[c * MROWS + m];
    }
}

extern "C" __global__ void __launch_bounds__(THREADS, 1)
anode_kernel(const float* __restrict__ ts, const float* __restrict__ y0,
             const float* __restrict__ b1, const float* __restrict__ b2,
             const float* __restrict__ b3,
             float* __restrict__ out, int out_size)
{
    extern __shared__ float sm[];
    float* tssm = sm;                        // 128
    float* b1s  = tssm + 128;                // 256
    float* b2s  = b1s + 256;                 // 256
    float* b3s  = b2s + 256;                 // 128
    float* y    = b3s + 128;                 // 2048
    float* ytmp = y    + MD;                 // 2048
    float* h1   = ytmp + MD;                 // 4096
    float* h2   = h1   + MROWS * WIDTHV;     // 4096
    float* ks   = h2   + MROWS * WIDTHV;     // 6*MD = 12288
    float* red  = ks   + 6 * MD;             // 512*33 = 16896

    const int tid  = threadIdx.x;
    const int base = blockIdx.x * MROWS;

    if (tid < TSTEPS) tssm[tid] = ts[tid];
    if (tid < WIDTHV) { b1s[tid] = b1[tid]; b2s[tid] = b2[tid]; }
    if (tid < DIMV)   b3s[tid] = b3[tid];

    // load batch tile, transposing to [channel][m]
    {
        int m  = tid & 15;
        int c4 = (tid >> 4) << 2;   // 32 groups * 4 = DIMV channels
        float4 v = *reinterpret_cast<const float4*>(y0 + (size_t)(base + m) * DIMV + c4);
        y[(c4 + 0) * MROWS + m] = v.x;
        y[(c4 + 1) * MROWS + m] = v.y;
        y[(c4 + 2) * MROWS + m] = v.z;
        y[(c4 + 3) * MROWS + m] = v.w;
    }
    __syncthreads();

    save_state(y, out, base, 0, tid);

    // Dopri5 tableau rows (combine coefficients applied AFTER each eval)
    const float c2_[1] = {0.2f};
    const float c3_[2] = {3.f/40.f, 9.f/40.f};
    const float c4_[3] = {44.f/45.f, -56.f/15.f, 32.f/9.f};
    const float c5_[4] = {19372.f/6561.f, -25360.f/2187.f, 64448.f/6561.f, -212.f/729.f};
    const float c6_[5] = {9017.f/3168.f, -355.f/33.f, 46732.f/5247.f, 49.f/176.f, -5103.f/18656.f};
    const float cb_[6] = {35.f/384.f, 0.f, 500.f/1113.f, 125.f/192.f, -2187.f/6784.f, 11.f/84.f};

#pragma unroll 1
    for (int t = 1; t < TSTEPS; ++t) {
        float dt = (tssm[t] - tssm[t - 1]) * (1.0f / SUBSTEPS);
#pragma unroll 1
        for (int s = 0; s < SUBSTEPS; ++s) {
            layer256<DIMV>  (y,    h1, g_W1t, b1s, red, tid);
            layer256<WIDTHV>(h1,   h2, g_W2t, b2s, red, tid);
            layer_out_fused<1>(h2, ks, y, ytmp, b3s, red, dt, c2_, tid);

            layer256<DIMV>  (ytmp, h1, g_W1t, b1s, red, tid);
            layer256<WIDTHV>(h1,   h2, g_W2t, b2s, red, tid);
            layer_out_fused<2>(h2, ks, y, ytmp, b3s, red, dt, c3_, tid);

            layer256<DIMV>  (ytmp, h1, g_W1t, b1s, red, tid);
            layer256<WIDTHV>(h1,   h2, g_W2t, b2s, red, tid);
            layer_out_fused<3>(h2, ks, y, ytmp, b3s, red, dt, c4_, tid);

            layer256<DIMV>  (ytmp, h1, g_W1t, b1s, red, tid);
            layer256<WIDTHV>(h1,   h2, g_W2t, b2s, red, tid);
            layer_out_fused<4>(h2, ks, y, ytmp, b3s, red, dt, c5_, tid);

            layer256<DIMV>  (ytmp, h1, g_W1t, b1s, red, tid);
            layer256<WIDTHV>(h1,   h2, g_W2t, b2s, red, tid);
            layer_out_fused<5>(h2, ks, y, ytmp, b3s, red, dt, c6_, tid);

            layer256<DIMV>  (ytmp, h1, g_W1t, b1s, red, tid);
            layer256<WIDTHV>(h1,   h2, g_W2t, b2s, red, tid);
            layer_out_fused<6>(h2, ks, y, y,    b3s, red, dt, cb_, tid);
        }
        save_state(y, out, base, t, tid);
    }

    // second reference output: num_steps = (T-1)*SUBSTEPS = 508
    if (blockIdx.x == 0 && tid == 0) {
        const long long TOT = (long long)TSTEPS * BATCH * DATAV;
        for (long long i = TOT; i < (long long)out_size; ++i)
            out[i] = 508.0f;
    }
}

extern "C" void kernel_launch(void* const* d_in, const int* in_sizes, int n_in,
                              void* d_out, int out_size)
{
    const float* ts = (const float*)d_in[0];
    const float* y0 = (const float*)d_in[1];
    const float* W1 = (const float*)d_in[2];
    const float* b1 = (const float*)d_in[3];
    const float* W2 = (const float*)d_in[4];
    const float* b2 = (const float*)d_in[5];
    const float* W3 = (const float*)d_in[6];
    const float* b3 = (const float*)d_in[7];
    float* out = (float*)d_out;

    transpose_weights<<<256, 256>>>(W1, W2, W3);

    // smem floats: 768 + 2*2048 + 2*4096 + 12288 + 16896 = 42240 -> 168,960 B
    const int smem_bytes = (768 + 2 * MD + 2 * MROWS * WIDTHV + 6 * MD + THREADS * 33)
                           * (int)sizeof(float);
    cudaFuncSetAttribute(anode_kernel,
                         cudaFuncAttributeMaxDynamicSharedMemorySize, smem_bytes);

    anode_kernel<<<GRIDN, THREADS, smem_bytes>>>(ts, y0, b1, b2, b3, out, out_size);
}